// round 15
// baseline (speedup 1.0000x reference)
#include <cuda_runtime.h>
#include <cuda_bf16.h>
#include <cuda_fp16.h>
#include <cstdint>

// Problem constants
#define BB 4
#define NN 10000
#define EE 170000
#define F_IN 256
#define FF 128
#define HH 4
#define MROWS (BB * NN)             // 40000
#define CCOLS (HH * FF)             // 512
#define NODE_STRIDE (BB * HH * FF)  // 2048 elements per node
#define BM 128
#define BN 64
#define MTILES 313                  // ceil(40000/128)
#define MPAD (MTILES * BM)          // 40064

// Merged-prep block ranges
#define PXB 5008                    // prep_x blocks: MPAD*32/256
#define PWB 64                      // prep_w blocks
#define PAB 8                       // prep_wa blocks
#define RSB 40                      // rowstart blocks
#define PREP_BLOCKS (PXB + PWB + PAB + RSB)

// Scratch (device globals; no allocation allowed)
__device__ __align__(16) __half g_h16[(size_t)NN * NODE_STRIDE];  // fp16 h (41MB)
__device__ float g_ps[HH * NN];
__device__ float g_pd[HH * NN];
__device__ int   g_rowstart[NN + 1];
__device__ __align__(16) float g_wa[8 * F_IN];   // [src h0-3 | dst h0-3][k]
__device__ float g_wac[8];                        // bias dot a
// fp16 images, row-major
__device__ __align__(16) __half g_Ah[(size_t)MPAD * F_IN];
__device__ __align__(16) __half g_Bh[HH * FF * F_IN];   // [head][f][k]

static __device__ __forceinline__ uint32_t smem_u32(const void* p) {
    uint32_t a;
    asm("{ .reg .u64 t; cvta.to.shared.u64 t, %1; cvt.u32.u64 %0, t; }" : "=r"(a) : "l"(p));
    return a;
}
static __device__ __forceinline__ void cp16(uint32_t dst, const void* src) {
    asm volatile("cp.async.cg.shared.global [%0], [%1], 16;" :: "r"(dst), "l"(src));
}
static __device__ __forceinline__ void ldm_x4(uint32_t& r0, uint32_t& r1, uint32_t& r2,
                                              uint32_t& r3, uint32_t addr) {
    asm volatile("ldmatrix.sync.aligned.m8n8.x4.shared.b16 {%0,%1,%2,%3}, [%4];"
                 : "=r"(r0), "=r"(r1), "=r"(r2), "=r"(r3) : "r"(addr));
}
static __device__ __forceinline__ void mma_f16(float* c, const uint32_t* a, const uint32_t* b) {
    asm volatile(
        "mma.sync.aligned.m16n8k16.row.col.f32.f16.f16.f32 "
        "{%0,%1,%2,%3}, {%4,%5,%6,%7}, {%8,%9}, {%0,%1,%2,%3};"
        : "+f"(c[0]), "+f"(c[1]), "+f"(c[2]), "+f"(c[3])
        : "r"(a[0]), "r"(a[1]), "r"(a[2]), "r"(a[3]), "r"(b[0]), "r"(b[1]));
}
static __device__ __forceinline__ __half2 u2h2(uint32_t u) {
    return *reinterpret_cast<__half2*>(&u);
}

// ---------------------------------------------------------------------------
// Merged prep: one launch, block-range dispatch.
// ---------------------------------------------------------------------------
__global__ __launch_bounds__(256) void prep_all(const float* __restrict__ x,
                                                const float* __restrict__ W,
                                                const float* __restrict__ bias,
                                                const float* __restrict__ Wattn,
                                                const int* __restrict__ src)
{
    const int blk = blockIdx.x;
    const int tid = threadIdx.x;

    if (blk < PXB) {
        // ---- prep_x ----
        int idx = blk * 256 + tid;           // m*32 + kgroup
        int m  = idx >> 5;
        int kg = (idx & 31) << 3;

        float v[8];
        if (m < MROWS) {
            const float4* p = (const float4*)(x + (size_t)m * F_IN + kg);
            float4 a = p[0], b = p[1];
            v[0] = a.x; v[1] = a.y; v[2] = a.z; v[3] = a.w;
            v[4] = b.x; v[5] = b.y; v[6] = b.z; v[7] = b.w;
        } else {
            #pragma unroll
            for (int j = 0; j < 8; j++) v[j] = 0.f;
        }
        __half h8[8];
        #pragma unroll
        for (int j = 0; j < 8; j++) h8[j] = __float2half_rn(v[j]);
        *(uint4*)(g_Ah + (size_t)m * F_IN + kg) = *(const uint4*)h8;
    } else if (blk < PXB + PWB) {
        // ---- prep_w ----
        int idx = (blk - PXB) * 256 + tid;   // head*4096 + f*32 + kgroup
        int head = idx >> 12;
        int f    = (idx >> 5) & 127;
        int kg   = (idx & 31) << 3;

        __half h8[8];
        #pragma unroll
        for (int j = 0; j < 8; j++)
            h8[j] = __float2half_rn(W[(size_t)head * F_IN * FF + (size_t)(kg + j) * FF + f]);
        *(uint4*)(g_Bh + ((size_t)head * FF + f) * F_IN + kg) = *(const uint4*)h8;
    } else if (blk < PXB + PWB + PAB) {
        // ---- prep_wa ----
        const int vec = blk - PXB - PWB;     // 0..7
        const int h = vec & 3;
        const int which = vec >> 2;
        const float* a = Wattn + h * (2 * FF) + which * FF;

        int k = tid;
        const float* wr = W + (size_t)h * F_IN * FF + (size_t)k * FF;
        float s = 0.f;
        #pragma unroll 4
        for (int f = 0; f < FF; f++) s = fmaf(wr[f], a[f], s);
        g_wa[vec * F_IN + k] = s;
        if (tid == 0) {
            float c = 0.f;
            for (int f = 0; f < FF; f++) c = fmaf(bias[h * FF + f], a[f], c);
            g_wac[vec] = c;
        }
    } else {
        // ---- rowstart ----
        int n = (blk - PXB - PWB - PAB) * 256 + tid;
        if (n > NN) return;
        int lo = 0, hi = EE;
        while (lo < hi) {
            int mid = (lo + hi) >> 1;
            if (src[mid] < n) lo = mid + 1; else hi = mid;
        }
        g_rowstart[n] = lo;
    }
}

// ---------------------------------------------------------------------------
// pvec: p_src/p_dst[h][n] = x[B-1][n][:] . Wa[vec][:] + wac[vec]  (fp32 exact)
// ---------------------------------------------------------------------------
__global__ __launch_bounds__(256) void pvec_kernel(const float* __restrict__ x)
{
    const int warp = (blockIdx.x * 256 + threadIdx.x) >> 5;
    const int lane = threadIdx.x & 31;
    if (warp >= NN) return;
    const int n = warp;
    const int kg = lane << 3;

    float v[8];
    const float4* p = (const float4*)(x + ((size_t)(BB - 1) * NN + n) * F_IN + kg);
    float4 a = p[0], b = p[1];
    v[0] = a.x; v[1] = a.y; v[2] = a.z; v[3] = a.w;
    v[4] = b.x; v[5] = b.y; v[6] = b.z; v[7] = b.w;

    float part[8];
    #pragma unroll
    for (int vec = 0; vec < 8; vec++) {
        const float* wa = g_wa + vec * F_IN + kg;
        float s = 0.f;
        #pragma unroll
        for (int j = 0; j < 8; j++) s = fmaf(v[j], wa[j], s);
        part[vec] = s;
    }
    #pragma unroll
    for (int o = 16; o > 0; o >>= 1)
        #pragma unroll
        for (int vec = 0; vec < 8; vec++)
            part[vec] += __shfl_down_sync(0xffffffffu, part[vec], o);
    if (lane == 0) {
        #pragma unroll
        for (int h = 0; h < 4; h++) {
            g_ps[h * NN + n] = part[h] + g_wac[h];
            g_pd[h * NN + n] = part[4 + h] + g_wac[4 + h];
        }
    }
}

// ---------------------------------------------------------------------------
// Tensor-core GEMM, single-pass fp16 (fp32 accum). CTA 128m x 64n, BK=64,
// 4 stages (whole K prefetched upfront, 96KB smem -> 2 CTAs/SM).
// ---------------------------------------------------------------------------
#define BK 64
#define A_SUB 16384
#define B_SUB 8192
#define STAGE_BYTES (A_SUB + B_SUB)           // 24576
#define NSTAGE 4
#define GEMM_SMEM (NSTAGE * STAGE_BYTES)      // 98304

static __device__ __forceinline__ uint32_t sw_off(int row, int chunk) {
    return (uint32_t)(row * 128 + ((chunk ^ (row & 7)) << 4));
}

__global__ __launch_bounds__(256, 2) void gemm_mma(const float* __restrict__ bias)
{
    extern __shared__ __align__(16) unsigned char smem[];
    const uint32_t sb = smem_u32(smem);
    const int tid  = threadIdx.x;
    const int wid  = tid >> 5;
    const int lane = tid & 31;
    const int head = blockIdx.x >> 1;
    const int nh   = blockIdx.x & 1;
    const int tile = blockIdx.y;

    const __half* gA = g_Ah + (size_t)tile * BM * F_IN;
    const __half* gB = g_Bh + ((size_t)head * FF + nh * BN) * F_IN;

    const int mw = wid & 3;
    const int nw = wid >> 2;

    float acc[2][4][4];
    #pragma unroll
    for (int i = 0; i < 2; i++)
        #pragma unroll
        for (int j = 0; j < 4; j++)
            #pragma unroll
            for (int q = 0; q < 4; q++) acc[i][j][q] = 0.f;

    auto prefetch = [&](int stage, int kc0) {
        uint32_t sdst = sb + stage * STAGE_BYTES;
        #pragma unroll
        for (int i = 0; i < 4; i++) {
            int idx = tid + i * 256;
            int row = idx >> 3;
            int ch  = idx & 7;
            cp16(sdst + sw_off(row, ch), gA + (size_t)row * F_IN + kc0 + ch * 8);
        }
        #pragma unroll
        for (int i = 0; i < 2; i++) {
            int idx = tid + i * 256;
            int row = idx >> 3;
            int ch  = idx & 7;
            cp16(sdst + A_SUB + sw_off(row, ch), gB + (size_t)row * F_IN + kc0 + ch * 8);
        }
        asm volatile("cp.async.commit_group;" ::: "memory");
    };

    prefetch(0, 0);
    prefetch(1, BK);
    prefetch(2, 2 * BK);
    prefetch(3, 3 * BK);

    const int a_row = mw * 32 + (lane & 7) + ((lane >> 3 & 1) << 3);
    const int a_chx = lane >> 4;
    const int b_row = nw * 32 + (lane & 7) + ((lane >> 4) << 3);
    const int b_chx = (lane >> 3) & 1;

    #pragma unroll
    for (int c = 0; c < 4; c++) {
        if (c == 0)      asm volatile("cp.async.wait_group 3;" ::: "memory");
        else if (c == 1) asm volatile("cp.async.wait_group 2;" ::: "memory");
        else if (c == 2) asm volatile("cp.async.wait_group 1;" ::: "memory");
        else             asm volatile("cp.async.wait_group 0;" ::: "memory");
        __syncthreads();

        const uint32_t stb = sb + c * STAGE_BYTES;
        #pragma unroll
        for (int ks = 0; ks < 4; ks++) {
            const int c0 = ks * 2;
            uint32_t a[2][4];
            #pragma unroll
            for (int mi = 0; mi < 2; mi++)
                ldm_x4(a[mi][0], a[mi][1], a[mi][2], a[mi][3],
                       stb + sw_off(a_row + mi * 16, c0 + a_chx));
            uint32_t b[4][2];
            #pragma unroll
            for (int j = 0; j < 2; j++) {
                uint32_t r0, r1, r2, r3;
                ldm_x4(r0, r1, r2, r3,
                       stb + A_SUB + sw_off(b_row + j * 16, c0 + b_chx));
                b[2 * j][0] = r0; b[2 * j][1] = r1;
                b[2 * j + 1][0] = r2; b[2 * j + 1][1] = r3;
            }
            #pragma unroll
            for (int mi = 0; mi < 2; mi++)
                #pragma unroll
                for (int ni = 0; ni < 4; ni++)
                    mma_f16(acc[mi][ni], a[mi], b[ni]);
        }
    }

    // Epilogue: add bias; write fp16 h
    const int col0 = nw * 32 + 2 * (lane & 3);
    #pragma unroll
    for (int mi = 0; mi < 2; mi++) {
        const int rl = mw * 32 + mi * 16 + (lane >> 2);
        #pragma unroll
        for (int half = 0; half < 2; half++) {
            const int m = tile * BM + rl + half * 8;
            if (m >= MROWS) continue;
            const int bidx = m / NN;
            const int n = m - bidx * NN;
            __half* op16 = g_h16 + (size_t)n * NODE_STRIDE + bidx * (HH * FF)
                         + head * FF + nh * BN;
            const float* bp = bias + head * FF + nh * BN;
            #pragma unroll
            for (int ni = 0; ni < 4; ni++) {
                const int col = col0 + ni * 8;
                float ox = acc[mi][ni][half * 2 + 0] + bp[col];
                float oy = acc[mi][ni][half * 2 + 1] + bp[col + 1];
                *(__half2*)(op16 + col) = __floats2half2_rn(ox, oy);
            }
        }
    }
}

// ---------------------------------------------------------------------------
// Aggregation (one block per src node). fp16 pairwise gather, fp32 accum.
//  - weights: fp32 (denominator) + broadcast half2 (numerator)
//  - denominator: warp-parallel (warps 0-3 = heads 0-3, shfl reduce)
//  - gather: 2 edges/iter, fp16 product pair summed in fp16, then fp32 accum
// ---------------------------------------------------------------------------
#define ACHUNK 128
__global__ __launch_bounds__(256) void agg_kernel(
    const int* __restrict__ dst,
    float* __restrict__ out)
{
    const int n = blockIdx.x;
    const int t = threadIdx.x;
    const int wid = t >> 5;
    const int lane = t & 31;
    const int e0 = g_rowstart[n];
    const int e1 = g_rowstart[n + 1];

    const int base = t * 8;              // 2048 elems = 256 threads * 8
    const int hi = (base >> 7) & 3;
    const int b  = base >> 9;

    __shared__ int      s_dst[ACHUNK];
    __shared__ float    s_w[HH][ACHUNK];
    __shared__ uint32_t s_wh[HH][ACHUNK];   // (w,w) packed half2
    __shared__ float    s_den[HH];

    float acc[8];
    #pragma unroll
    for (int j = 0; j < 8; j++) acc[j] = 0.f;
    float den = 0.f;                     // meaningful on lane 0 of warps 0-3

    for (int cs = e0; cs < e1; cs += ACHUNK) {
        const int m = min(cs + ACHUNK, e1) - cs;
        if (t < m) {
            int d = dst[cs + t];
            s_dst[t] = d;
            #pragma unroll
            for (int h = 0; h < HH; h++) {
                float s = g_ps[h * NN + n] + g_pd[h * NN + d];
                s = (s >= 0.f) ? s : 0.2f * s;
                s = fminf(fmaxf(s, -2.f), 2.f);
                float w = __expf(s);
                s_w[h][t] = w;
                __half hw = __float2half_rn(w);
                __half2 hw2 = __halves2half2(hw, hw);
                s_wh[h][t] = *reinterpret_cast<uint32_t*>(&hw2);
            }
        }
        __syncthreads();

        // warp-parallel denominator: warp w handles head w
        if (wid < HH) {
            float p = 0.f;
            #pragma unroll
            for (int j = 0; j < 4; j++) {
                int e = lane + 32 * j;
                if (e < m) p += s_w[wid][e];
            }
            #pragma unroll
            for (int o = 16; o > 0; o >>= 1)
                p += __shfl_down_sync(0xffffffffu, p, o);
            if (lane == 0) den += p;
        }

        // gather: 2 edges per iteration (fp16 pair products)
        int e = 0;
        #pragma unroll 2
        for (; e + 2 <= m; e += 2) {
            __half2 w0 = u2h2(s_wh[hi][e]);
            __half2 w1 = u2h2(s_wh[hi][e + 1]);
            uint4 v0 = *(const uint4*)(g_h16 + (size_t)s_dst[e] * NODE_STRIDE + base);
            uint4 v1 = *(const uint4*)(g_h16 + (size_t)s_dst[e + 1] * NODE_STRIDE + base);
            __half2 p0 = __hfma2(u2h2(v1.x), w1, __hmul2(u2h2(v0.x), w0));
            __half2 p1 = __hfma2(u2h2(v1.y), w1, __hmul2(u2h2(v0.y), w0));
            __half2 p2 = __hfma2(u2h2(v1.z), w1, __hmul2(u2h2(v0.z), w0));
            __half2 p3 = __hfma2(u2h2(v1.w), w1, __hmul2(u2h2(v0.w), w0));
            float2 f0 = __half22float2(p0);
            float2 f1 = __half22float2(p1);
            float2 f2 = __half22float2(p2);
            float2 f3 = __half22float2(p3);
            acc[0] += f0.x; acc[1] += f0.y;
            acc[2] += f1.x; acc[3] += f1.y;
            acc[4] += f2.x; acc[5] += f2.y;
            acc[6] += f3.x; acc[7] += f3.y;
        }
        if (e < m) {                     // odd tail
            __half2 w0 = u2h2(s_wh[hi][e]);
            uint4 v0 = *(const uint4*)(g_h16 + (size_t)s_dst[e] * NODE_STRIDE + base);
            __half2 p0 = __hmul2(u2h2(v0.x), w0);
            __half2 p1 = __hmul2(u2h2(v0.y), w0);
            __half2 p2 = __hmul2(u2h2(v0.z), w0);
            __half2 p3 = __hmul2(u2h2(v0.w), w0);
            float2 f0 = __half22float2(p0);
            float2 f1 = __half22float2(p1);
            float2 f2 = __half22float2(p2);
            float2 f3 = __half22float2(p3);
            acc[0] += f0.x; acc[1] += f0.y;
            acc[2] += f1.x; acc[3] += f1.y;
            acc[4] += f2.x; acc[5] += f2.y;
            acc[6] += f3.x; acc[7] += f3.y;
        }
        __syncthreads();
    }

    if (wid < HH && lane == 0) s_den[wid] = den;
    __syncthreads();

    float inv = (e1 > e0) ? (1.f / s_den[hi]) : 0.f;
    float* op = out + ((size_t)b * NN + n) * CCOLS + (base & (CCOLS - 1));
    float4 o0, o1;
    o0.x = acc[0] * inv; o0.y = acc[1] * inv; o0.z = acc[2] * inv; o0.w = acc[3] * inv;
    o1.x = acc[4] * inv; o1.y = acc[5] * inv; o1.z = acc[6] * inv; o1.w = acc[7] * inv;
    ((float4*)op)[0] = o0;
    ((float4*)op)[1] = o1;
}

// ---------------------------------------------------------------------------
// Launch
// ---------------------------------------------------------------------------
extern "C" void kernel_launch(void* const* d_in, const int* in_sizes, int n_in,
                              void* d_out, int out_size)
{
    const float* x     = (const float*)d_in[0];
    const float* Wmlp  = (const float*)d_in[1];
    const float* bmlp  = (const float*)d_in[2];
    const float* Wattn = (const float*)d_in[3];
    const int*   src   = (const int*)d_in[4];
    const int*   dst   = (const int*)d_in[5];
    float*       out   = (float*)d_out;

    (void)in_sizes; (void)n_in; (void)out_size;

    cudaFuncSetAttribute(gemm_mma, cudaFuncAttributeMaxDynamicSharedMemorySize, GEMM_SMEM);

    prep_all<<<PREP_BLOCKS, 256>>>(x, Wmlp, bmlp, Wattn, src);
    pvec_kernel<<<(NN + 7) / 8, 256>>>(x);

    gemm_mma<<<dim3(HH * 2, MTILES), 256, GEMM_SMEM>>>(bmlp);

    agg_kernel<<<NN, 256>>>(dst, out);
}

// round 17
// speedup vs baseline: 1.0738x; 1.0738x over previous
#include <cuda_runtime.h>
#include <cuda_bf16.h>
#include <cuda_fp16.h>
#include <cstdint>

// Problem constants
#define BB 4
#define NN 10000
#define EE 170000
#define F_IN 256
#define FF 128
#define HH 4
#define MROWS (BB * NN)             // 40000
#define CCOLS (HH * FF)             // 512
#define NODE_STRIDE (BB * HH * FF)  // 2048 elements per node
#define BM 128
#define BN 64
#define MTILES 313                  // ceil(40000/128)
#define MPAD (MTILES * BM)          // 40064

// Merged-prep block ranges
#define PXB 5008                    // prep_x blocks: MPAD*32/256
#define PWB 64                      // prep_w blocks
#define PAB 8                       // prep_wa blocks
#define RSB 40                      // rowstart blocks
#define PREP_BLOCKS (PXB + PWB + PAB + RSB)

// gemm+pvec merged launch
#define GEMM_BLOCKS (HH * 2 * MTILES)        // 2504
#define PVEC_BLOCKS ((NN + 7) / 8)           // 1250
#define GP_BLOCKS (GEMM_BLOCKS + PVEC_BLOCKS)

// Scratch (device globals; no allocation allowed)
__device__ __align__(16) __half g_h16[(size_t)NN * NODE_STRIDE];  // fp16 h (41MB)
__device__ float g_ps[HH * NN];
__device__ float g_pd[HH * NN];
__device__ int   g_rowstart[NN + 1];
__device__ __align__(16) float g_wa[8 * F_IN];   // [src h0-3 | dst h0-3][k]
__device__ float g_wac[8];                        // bias dot a
// fp16 images, row-major
__device__ __align__(16) __half g_Ah[(size_t)MPAD * F_IN];
__device__ __align__(16) __half g_Bh[HH * FF * F_IN];   // [head][f][k]

static __device__ __forceinline__ uint32_t smem_u32(const void* p) {
    uint32_t a;
    asm("{ .reg .u64 t; cvta.to.shared.u64 t, %1; cvt.u32.u64 %0, t; }" : "=r"(a) : "l"(p));
    return a;
}
static __device__ __forceinline__ void cp16(uint32_t dst, const void* src) {
    asm volatile("cp.async.cg.shared.global [%0], [%1], 16;" :: "r"(dst), "l"(src));
}
static __device__ __forceinline__ void ldm_x4(uint32_t& r0, uint32_t& r1, uint32_t& r2,
                                              uint32_t& r3, uint32_t addr) {
    asm volatile("ldmatrix.sync.aligned.m8n8.x4.shared.b16 {%0,%1,%2,%3}, [%4];"
                 : "=r"(r0), "=r"(r1), "=r"(r2), "=r"(r3) : "r"(addr));
}
static __device__ __forceinline__ void mma_f16(float* c, const uint32_t* a, const uint32_t* b) {
    asm volatile(
        "mma.sync.aligned.m16n8k16.row.col.f32.f16.f16.f32 "
        "{%0,%1,%2,%3}, {%4,%5,%6,%7}, {%8,%9}, {%0,%1,%2,%3};"
        : "+f"(c[0]), "+f"(c[1]), "+f"(c[2]), "+f"(c[3])
        : "r"(a[0]), "r"(a[1]), "r"(a[2]), "r"(a[3]), "r"(b[0]), "r"(b[1]));
}

// ---------------------------------------------------------------------------
// Merged prep: one launch, block-range dispatch.
// ---------------------------------------------------------------------------
__global__ __launch_bounds__(256) void prep_all(const float* __restrict__ x,
                                                const float* __restrict__ W,
                                                const float* __restrict__ bias,
                                                const float* __restrict__ Wattn,
                                                const int* __restrict__ src)
{
    const int blk = blockIdx.x;
    const int tid = threadIdx.x;

    if (blk < PXB) {
        // ---- prep_x ----
        int idx = blk * 256 + tid;           // m*32 + kgroup
        int m  = idx >> 5;
        int kg = (idx & 31) << 3;

        float v[8];
        if (m < MROWS) {
            const float4* p = (const float4*)(x + (size_t)m * F_IN + kg);
            float4 a = p[0], b = p[1];
            v[0] = a.x; v[1] = a.y; v[2] = a.z; v[3] = a.w;
            v[4] = b.x; v[5] = b.y; v[6] = b.z; v[7] = b.w;
        } else {
            #pragma unroll
            for (int j = 0; j < 8; j++) v[j] = 0.f;
        }
        __half h8[8];
        #pragma unroll
        for (int j = 0; j < 8; j++) h8[j] = __float2half_rn(v[j]);
        *(uint4*)(g_Ah + (size_t)m * F_IN + kg) = *(const uint4*)h8;
    } else if (blk < PXB + PWB) {
        // ---- prep_w ----
        int idx = (blk - PXB) * 256 + tid;   // head*4096 + f*32 + kgroup
        int head = idx >> 12;
        int f    = (idx >> 5) & 127;
        int kg   = (idx & 31) << 3;

        __half h8[8];
        #pragma unroll
        for (int j = 0; j < 8; j++)
            h8[j] = __float2half_rn(W[(size_t)head * F_IN * FF + (size_t)(kg + j) * FF + f]);
        *(uint4*)(g_Bh + ((size_t)head * FF + f) * F_IN + kg) = *(const uint4*)h8;
    } else if (blk < PXB + PWB + PAB) {
        // ---- prep_wa ----
        const int vec = blk - PXB - PWB;     // 0..7
        const int h = vec & 3;
        const int which = vec >> 2;
        const float* a = Wattn + h * (2 * FF) + which * FF;

        int k = tid;
        const float* wr = W + (size_t)h * F_IN * FF + (size_t)k * FF;
        float s = 0.f;
        #pragma unroll 4
        for (int f = 0; f < FF; f++) s = fmaf(wr[f], a[f], s);
        g_wa[vec * F_IN + k] = s;
        if (tid == 0) {
            float c = 0.f;
            for (int f = 0; f < FF; f++) c = fmaf(bias[h * FF + f], a[f], c);
            g_wac[vec] = c;
        }
    } else {
        // ---- rowstart ----
        int n = (blk - PXB - PWB - PAB) * 256 + tid;
        if (n > NN) return;
        int lo = 0, hi = EE;
        while (lo < hi) {
            int mid = (lo + hi) >> 1;
            if (src[mid] < n) lo = mid + 1; else hi = mid;
        }
        g_rowstart[n] = lo;
    }
}

// ---------------------------------------------------------------------------
// GEMM (+ merged pvec blocks). Single-pass fp16 mma, fp32 accum.
// blocks [0, GEMM_BLOCKS): CTA 128m x 64n, BK=64, 4 stages (96KB, 2 CTA/SM).
//   tile = blk>>3, head = (blk&7)>>1, nh = blk&1  (8 CTAs share one A tile)
// blocks [GEMM_BLOCKS, GP_BLOCKS): pvec — p_src/p_dst from x . Wa (fp32).
// ---------------------------------------------------------------------------
#define BK 64
#define A_SUB 16384
#define B_SUB 8192
#define STAGE_BYTES (A_SUB + B_SUB)           // 24576
#define NSTAGE 4
#define GEMM_SMEM (NSTAGE * STAGE_BYTES)      // 98304

static __device__ __forceinline__ uint32_t sw_off(int row, int chunk) {
    return (uint32_t)(row * 128 + ((chunk ^ (row & 7)) << 4));
}

__global__ __launch_bounds__(256, 2) void gemm_mma(const float* __restrict__ bias,
                                                   const float* __restrict__ x)
{
    const int tid  = threadIdx.x;

    if (blockIdx.x >= GEMM_BLOCKS) {
        // ---------------- pvec path ----------------
        const int warp = ((blockIdx.x - GEMM_BLOCKS) * 256 + tid) >> 5;
        const int lane = tid & 31;
        if (warp >= NN) return;
        const int n = warp;
        const int kg = lane << 3;

        float v[8];
        const float4* p = (const float4*)(x + ((size_t)(BB - 1) * NN + n) * F_IN + kg);
        float4 a = p[0], b = p[1];
        v[0] = a.x; v[1] = a.y; v[2] = a.z; v[3] = a.w;
        v[4] = b.x; v[5] = b.y; v[6] = b.z; v[7] = b.w;

        float part[8];
        #pragma unroll
        for (int vec = 0; vec < 8; vec++) {
            const float* wa = g_wa + vec * F_IN + kg;
            float s = 0.f;
            #pragma unroll
            for (int j = 0; j < 8; j++) s = fmaf(v[j], wa[j], s);
            part[vec] = s;
        }
        #pragma unroll
        for (int o = 16; o > 0; o >>= 1)
            #pragma unroll
            for (int vec = 0; vec < 8; vec++)
                part[vec] += __shfl_down_sync(0xffffffffu, part[vec], o);
        if (lane == 0) {
            #pragma unroll
            for (int h = 0; h < 4; h++) {
                g_ps[h * NN + n] = part[h] + g_wac[h];
                g_pd[h * NN + n] = part[4 + h] + g_wac[4 + h];
            }
        }
        return;
    }

    // ---------------- GEMM path ----------------
    extern __shared__ __align__(16) unsigned char smem[];
    const uint32_t sb = smem_u32(smem);
    const int wid  = tid >> 5;
    const int lane = tid & 31;
    const int tile = blockIdx.x >> 3;
    const int head = (blockIdx.x & 7) >> 1;
    const int nh   = blockIdx.x & 1;

    const __half* gA = g_Ah + (size_t)tile * BM * F_IN;
    const __half* gB = g_Bh + ((size_t)head * FF + nh * BN) * F_IN;

    const int mw = wid & 3;
    const int nw = wid >> 2;

    float acc[2][4][4];
    #pragma unroll
    for (int i = 0; i < 2; i++)
        #pragma unroll
        for (int j = 0; j < 4; j++)
            #pragma unroll
            for (int q = 0; q < 4; q++) acc[i][j][q] = 0.f;

    auto prefetch = [&](int stage, int kc0) {
        uint32_t sdst = sb + stage * STAGE_BYTES;
        #pragma unroll
        for (int i = 0; i < 4; i++) {
            int idx = tid + i * 256;
            int row = idx >> 3;
            int ch  = idx & 7;
            cp16(sdst + sw_off(row, ch), gA + (size_t)row * F_IN + kc0 + ch * 8);
        }
        #pragma unroll
        for (int i = 0; i < 2; i++) {
            int idx = tid + i * 256;
            int row = idx >> 3;
            int ch  = idx & 7;
            cp16(sdst + A_SUB + sw_off(row, ch), gB + (size_t)row * F_IN + kc0 + ch * 8);
        }
        asm volatile("cp.async.commit_group;" ::: "memory");
    };

    prefetch(0, 0);
    prefetch(1, BK);
    prefetch(2, 2 * BK);
    prefetch(3, 3 * BK);

    const int a_row = mw * 32 + (lane & 7) + ((lane >> 3 & 1) << 3);
    const int a_chx = lane >> 4;
    const int b_row = nw * 32 + (lane & 7) + ((lane >> 4) << 3);
    const int b_chx = (lane >> 3) & 1;

    #pragma unroll
    for (int c = 0; c < 4; c++) {
        if (c == 0)      asm volatile("cp.async.wait_group 3;" ::: "memory");
        else if (c == 1) asm volatile("cp.async.wait_group 2;" ::: "memory");
        else if (c == 2) asm volatile("cp.async.wait_group 1;" ::: "memory");
        else             asm volatile("cp.async.wait_group 0;" ::: "memory");
        __syncthreads();

        const uint32_t stb = sb + c * STAGE_BYTES;
        #pragma unroll
        for (int ks = 0; ks < 4; ks++) {
            const int c0 = ks * 2;
            uint32_t a[2][4];
            #pragma unroll
            for (int mi = 0; mi < 2; mi++)
                ldm_x4(a[mi][0], a[mi][1], a[mi][2], a[mi][3],
                       stb + sw_off(a_row + mi * 16, c0 + a_chx));
            uint32_t b[4][2];
            #pragma unroll
            for (int j = 0; j < 2; j++) {
                uint32_t r0, r1, r2, r3;
                ldm_x4(r0, r1, r2, r3,
                       stb + A_SUB + sw_off(b_row + j * 16, c0 + b_chx));
                b[2 * j][0] = r0; b[2 * j][1] = r1;
                b[2 * j + 1][0] = r2; b[2 * j + 1][1] = r3;
            }
            #pragma unroll
            for (int mi = 0; mi < 2; mi++)
                #pragma unroll
                for (int ni = 0; ni < 4; ni++)
                    mma_f16(acc[mi][ni], a[mi], b[ni]);
        }
    }

    // Epilogue: add bias; write fp16 h
    const int col0 = nw * 32 + 2 * (lane & 3);
    #pragma unroll
    for (int mi = 0; mi < 2; mi++) {
        const int rl = mw * 32 + mi * 16 + (lane >> 2);
        #pragma unroll
        for (int half = 0; half < 2; half++) {
            const int m = tile * BM + rl + half * 8;
            if (m >= MROWS) continue;
            const int bidx = m / NN;
            const int n = m - bidx * NN;
            __half* op16 = g_h16 + (size_t)n * NODE_STRIDE + bidx * (HH * FF)
                         + head * FF + nh * BN;
            const float* bp = bias + head * FF + nh * BN;
            #pragma unroll
            for (int ni = 0; ni < 4; ni++) {
                const int col = col0 + ni * 8;
                float ox = acc[mi][ni][half * 2 + 0] + bp[col];
                float oy = acc[mi][ni][half * 2 + 1] + bp[col + 1];
                *(__half2*)(op16 + col) = __floats2half2_rn(ox, oy);
            }
        }
    }
}

// ---------------------------------------------------------------------------
// Aggregation (one block per src node), fp16 gather, fp32 accum.
// (exact R14 version — best measured: 60.6us, occ 91%)
// ---------------------------------------------------------------------------
#define ACHUNK 128
__global__ __launch_bounds__(256) void agg_kernel(
    const int* __restrict__ dst,
    float* __restrict__ out)
{
    const int n = blockIdx.x;
    const int t = threadIdx.x;
    const int e0 = g_rowstart[n];
    const int e1 = g_rowstart[n + 1];

    const int base = t * 8;              // 2048 elems = 256 threads * 8
    const int hi = (base >> 7) & 3;
    const int b  = base >> 9;

    __shared__ int   s_dst[ACHUNK];
    __shared__ float s_w[HH][ACHUNK];
    __shared__ float s_den[HH];

    float acc[8];
    #pragma unroll
    for (int j = 0; j < 8; j++) acc[j] = 0.f;
    float den_local = 0.f;

    for (int cs = e0; cs < e1; cs += ACHUNK) {
        const int m = min(cs + ACHUNK, e1) - cs;
        if (t < m) {
            int e = cs + t;
            int d = dst[e];
            s_dst[t] = d;
            #pragma unroll
            for (int h = 0; h < HH; h++) {
                float s = g_ps[h * NN + n] + g_pd[h * NN + d];
                s = (s >= 0.f) ? s : 0.2f * s;
                s = fminf(fmaxf(s, -2.f), 2.f);
                s_w[h][t] = __expf(s);
            }
        }
        __syncthreads();

        if (t < HH) {
            float sm = 0.f;
            for (int e = 0; e < m; e++) sm += s_w[t][e];
            den_local += sm;
        }

        #pragma unroll 2
        for (int e = 0; e < m; e++) {
            float w = s_w[hi][e];
            uint4 v = *(const uint4*)(g_h16 + (size_t)s_dst[e] * NODE_STRIDE + base);
            float2 f0 = __half22float2(*reinterpret_cast<__half2*>(&v.x));
            float2 f1 = __half22float2(*reinterpret_cast<__half2*>(&v.y));
            float2 f2 = __half22float2(*reinterpret_cast<__half2*>(&v.z));
            float2 f3 = __half22float2(*reinterpret_cast<__half2*>(&v.w));
            acc[0] = fmaf(w, f0.x, acc[0]);
            acc[1] = fmaf(w, f0.y, acc[1]);
            acc[2] = fmaf(w, f1.x, acc[2]);
            acc[3] = fmaf(w, f1.y, acc[3]);
            acc[4] = fmaf(w, f2.x, acc[4]);
            acc[5] = fmaf(w, f2.y, acc[5]);
            acc[6] = fmaf(w, f3.x, acc[6]);
            acc[7] = fmaf(w, f3.y, acc[7]);
        }
        __syncthreads();
    }

    if (t < HH) s_den[t] = den_local;
    __syncthreads();

    float inv = (e1 > e0) ? (1.f / s_den[hi]) : 0.f;
    float* op = out + ((size_t)b * NN + n) * CCOLS + (base & (CCOLS - 1));
    float4 o0, o1;
    o0.x = acc[0] * inv; o0.y = acc[1] * inv; o0.z = acc[2] * inv; o0.w = acc[3] * inv;
    o1.x = acc[4] * inv; o1.y = acc[5] * inv; o1.z = acc[6] * inv; o1.w = acc[7] * inv;
    ((float4*)op)[0] = o0;
    ((float4*)op)[1] = o1;
}

// ---------------------------------------------------------------------------
// Launch
// ---------------------------------------------------------------------------
extern "C" void kernel_launch(void* const* d_in, const int* in_sizes, int n_in,
                              void* d_out, int out_size)
{
    const float* x     = (const float*)d_in[0];
    const float* Wmlp  = (const float*)d_in[1];
    const float* bmlp  = (const float*)d_in[2];
    const float* Wattn = (const float*)d_in[3];
    const int*   src   = (const int*)d_in[4];
    const int*   dst   = (const int*)d_in[5];
    float*       out   = (float*)d_out;

    (void)in_sizes; (void)n_in; (void)out_size;

    cudaFuncSetAttribute(gemm_mma, cudaFuncAttributeMaxDynamicSharedMemorySize, GEMM_SMEM);

    prep_all<<<PREP_BLOCKS, 256>>>(x, Wmlp, bmlp, Wattn, src);

    gemm_mma<<<GP_BLOCKS, 256, GEMM_SMEM>>>(bmlp, x);

    agg_kernel<<<NN, 256>>>(dst, out);
}